// round 11
// baseline (speedup 1.0000x reference)
#include <cuda_runtime.h>
#include <math.h>

// ---------------------------------------------------------------------------
// HRFormer block: B=8, C=384, H=W=112, WS=7, NH=12, head=32, HID=1536
// Tokens T = 8*112*112 = 100352 ; windows = 2048, 49 tokens each.
// All fp32. GEMMs use packed f32x2 FMA (FFMA2) for 2x fp32 throughput.
// ---------------------------------------------------------------------------

#define T_TOK 100352
#define NWIN  2048

// scratch (device globals: allocation-free)
__device__ float g_xn [38535168];   // T*384   LN1, windowed token order
__device__ float g_qkv[115605504];  // T*1152
__device__ float g_ao [38535168];   // T*384   attention out, windowed order
__device__ float g_po [38535168];   // T*384   proj out, windowed order
__device__ float g_y  [38535168];   // T*384   shortcut+attn, pixel order (NHWC)
__device__ float g_yn [38535168];   // T*384   LN2(y), pixel order
__device__ float g_h1 [154140672];  // T*1536  gelu(fc1)
__device__ float g_z  [38535168];   // T*384   y + fc2, pixel order

typedef unsigned long long u64;

__device__ __forceinline__ u64 pack2(float lo, float hi) {
    u64 r; asm("mov.b64 %0, {%1, %2};" : "=l"(r) : "f"(lo), "f"(hi)); return r;
}
__device__ __forceinline__ void unpack2(u64 v, float &lo, float &hi) {
    asm("mov.b64 {%0, %1}, %2;" : "=f"(lo), "=f"(hi) : "l"(v));
}
__device__ __forceinline__ void ffma2(u64 &d, u64 a, u64 b) {
    asm("fma.rn.f32x2 %0, %1, %2, %0;" : "+l"(d) : "l"(a), "l"(b));
}

// ---------------------------------------------------------------------------
// Kernel 1: LN1 over C + window partition.
// One block = 16 consecutive pixels of one image (tiles never cross a row:
// 112 = 7*16). Load x (NCHW) via smem transpose so global reads are coalesced.
// ---------------------------------------------------------------------------
__global__ void __launch_bounds__(256)
ln1_win(const float* __restrict__ x, const float* __restrict__ g,
        const float* __restrict__ b, float* __restrict__ xn)
{
    __shared__ float sm[16][388];
    const int bid = blockIdx.x;
    const int img = bid / 784;
    const int p0  = (bid % 784) * 16;
    const int tid = threadIdx.x;

    {
        const int p  = tid & 15;
        const int c0 = tid >> 4;
        const float* xb = x + (size_t)img * 384 * 12544 + p0;
        for (int c = c0; c < 384; c += 16)
            sm[p][c] = xb[(size_t)c * 12544 + p];
    }
    __syncthreads();

    const int pix = tid >> 4;
    const int sub = tid & 15;
    float s = 0.f, s2 = 0.f;
    for (int c = sub; c < 384; c += 16) { float v = sm[pix][c]; s += v; s2 += v*v; }
    for (int o = 8; o; o >>= 1) {
        s  += __shfl_xor_sync(0xffffffffu, s,  o, 16);
        s2 += __shfl_xor_sync(0xffffffffu, s2, o, 16);
    }
    const float mean = s * (1.f/384.f);
    const float var  = s2 * (1.f/384.f) - mean * mean;
    const float rstd = rsqrtf(var + 1e-5f);

    const int pg = p0 + pix;
    const int h = pg / 112, w = pg % 112;
    const int win = img * 256 + (h / 7) * 16 + (w / 7);
    const int n   = (h % 7) * 7 + (w % 7);
    const size_t t = (size_t)(win * 49 + n) * 384;
    for (int c = sub; c < 384; c += 16)
        xn[t + c] = (sm[pix][c] - mean) * rstd * g[c] + b[c];
}

// ---------------------------------------------------------------------------
// Generic 128x128x16 GEMM, 256 threads, 8x8 microtile, packed f32x2 FMA.
// C[M,N] = A[M,K] @ B[K,N] + bias, with optional GELU (EPI=1) or residual
// add (EPI=2). All dims assumed multiples of the tile (true here).
// ---------------------------------------------------------------------------
template<int EPI>
__global__ void __launch_bounds__(256)
gemm_kernel(const float* __restrict__ A, const float* __restrict__ B,
            const float* __restrict__ bias, const float* __restrict__ res,
            float* __restrict__ C, int M, int N, int K)
{
    __shared__ __align__(16) float As[16][132];
    __shared__ __align__(16) float Bs[16][132];

    const int tid = threadIdx.x;
    const int m0 = blockIdx.y * 128;
    const int n0 = blockIdx.x * 128;
    const int ty = tid >> 4;
    const int tx = tid & 15;

    const int am = tid >> 2;          // A tile row (0..63, +64)
    const int ak = (tid & 3) << 2;    // A tile col (float4)
    const int bk = tid >> 5;          // B tile row (0..7, +8)
    const int bn = (tid & 31) << 2;   // B tile col (float4)

    u64 acc[8][4];
#pragma unroll
    for (int i = 0; i < 8; i++)
#pragma unroll
        for (int j = 0; j < 4; j++) acc[i][j] = 0ULL;  // (0.f,0.f)

    const float* Aptr = A + (size_t)(m0 + am) * K + ak;
    const float* Bptr = B + (size_t)bk * N + n0 + bn;

    for (int kb = 0; kb < K; kb += 16) {
#pragma unroll
        for (int r = 0; r < 2; r++) {
            float4 av = *(const float4*)(Aptr + (size_t)(r * 64) * K + kb);
            const int mm = am + r * 64;
            As[ak + 0][mm] = av.x;
            As[ak + 1][mm] = av.y;
            As[ak + 2][mm] = av.z;
            As[ak + 3][mm] = av.w;
        }
#pragma unroll
        for (int r = 0; r < 2; r++)
            *(float4*)&Bs[bk + r * 8][bn] =
                *(const float4*)(Bptr + (size_t)(kb + r * 8) * N);
        __syncthreads();

#pragma unroll
        for (int k = 0; k < 16; k++) {
            const float4 a0 = *(const float4*)&As[k][ty * 8];
            const float4 a1 = *(const float4*)&As[k][ty * 8 + 4];
            const u64* bq = (const u64*)&Bs[k][tx * 8];
            const u64 bv0 = bq[0], bv1 = bq[1], bv2 = bq[2], bv3 = bq[3];
            u64 av[8];
            av[0] = pack2(a0.x, a0.x); av[1] = pack2(a0.y, a0.y);
            av[2] = pack2(a0.z, a0.z); av[3] = pack2(a0.w, a0.w);
            av[4] = pack2(a1.x, a1.x); av[5] = pack2(a1.y, a1.y);
            av[6] = pack2(a1.z, a1.z); av[7] = pack2(a1.w, a1.w);
#pragma unroll
            for (int i = 0; i < 8; i++) {
                ffma2(acc[i][0], av[i], bv0);
                ffma2(acc[i][1], av[i], bv1);
                ffma2(acc[i][2], av[i], bv2);
                ffma2(acc[i][3], av[i], bv3);
            }
        }
        __syncthreads();
    }

    float bcol[8];
#pragma unroll
    for (int j = 0; j < 8; j++) bcol[j] = bias[n0 + tx * 8 + j];

#pragma unroll
    for (int i = 0; i < 8; i++) {
        const int row = m0 + ty * 8 + i;
        const size_t rb = (size_t)row * N + n0 + tx * 8;
#pragma unroll
        for (int j = 0; j < 4; j++) {
            float lo, hi;
            unpack2(acc[i][j], lo, hi);
            lo += bcol[2 * j];
            hi += bcol[2 * j + 1];
            if (EPI == 1) {  // exact GELU
                lo = 0.5f * lo * (1.f + erff(lo * 0.7071067811865475f));
                hi = 0.5f * hi * (1.f + erff(hi * 0.7071067811865475f));
            }
            if (EPI == 2) {
                lo += res[rb + 2 * j];
                hi += res[rb + 2 * j + 1];
            }
            float2 st; st.x = lo; st.y = hi;
            *(float2*)(C + rb + 2 * j) = st;
        }
    }
}

// ---------------------------------------------------------------------------
// Kernel 3: windowed attention. One block = (window, head). 49 tokens, d=32.
// ---------------------------------------------------------------------------
__global__ void __launch_bounds__(128)
attn_kernel(const float* __restrict__ qkv, const float* __restrict__ rpb,
            float* __restrict__ ao)
{
    __shared__ float q [49][33];
    __shared__ float kk[49][33];
    __shared__ float vv[49][33];
    __shared__ float at[49][49];

    const int win  = blockIdx.x / 12;
    const int head = blockIdx.x % 12;
    const int tid  = threadIdx.x;

    const size_t base0 = (size_t)win * 49 * 1152 + head * 32;
    for (int i = tid; i < 49 * 32; i += 128) {
        const int n = i >> 5, d = i & 31;
        const size_t o = base0 + (size_t)n * 1152 + d;
        q [n][d] = qkv[o]       * 0.1767766952966369f;  // 32^-0.5
        kk[n][d] = qkv[o + 384];
        vv[n][d] = qkv[o + 768];
    }
    __syncthreads();

    for (int idx = tid; idx < 49 * 49; idx += 128) {
        const int n = idx / 49, m = idx % 49;
        float s = 0.f;
#pragma unroll
        for (int d = 0; d < 32; d++) s += q[n][d] * kk[m][d];
        const int i1 = n / 7, j1 = n % 7, i2 = m / 7, j2 = m % 7;
        const int ridx = (i1 - i2 + 6) * 13 + (j1 - j2 + 6);
        at[n][m] = s + rpb[ridx * 12 + head];
    }
    __syncthreads();

    if (tid < 49) {
        const int n = tid;
        float mx = -1e30f;
        for (int m = 0; m < 49; m++) mx = fmaxf(mx, at[n][m]);
        float sum = 0.f;
        for (int m = 0; m < 49; m++) { float e = expf(at[n][m] - mx); at[n][m] = e; sum += e; }
        const float inv = 1.f / sum;
        for (int m = 0; m < 49; m++) at[n][m] *= inv;
    }
    __syncthreads();

    for (int i = tid; i < 49 * 32; i += 128) {
        const int n = i >> 5, d = i & 31;
        float s = 0.f;
#pragma unroll
        for (int m = 0; m < 49; m++) s += at[n][m] * vv[m][d];
        ao[(size_t)(win * 49 + n) * 384 + head * 32 + d] = s;
    }
}

// ---------------------------------------------------------------------------
// Kernel 5: y = transpose(x) + window_reverse(proj_out); yn = LN2(y).
// Same tile structure as ln1_win.
// ---------------------------------------------------------------------------
__global__ void __launch_bounds__(256)
res_ln2(const float* __restrict__ x, const float* __restrict__ po,
        const float* __restrict__ g, const float* __restrict__ b,
        float* __restrict__ y, float* __restrict__ yn)
{
    __shared__ float sm[16][388];
    const int bid = blockIdx.x;
    const int img = bid / 784;
    const int p0  = (bid % 784) * 16;
    const int tid = threadIdx.x;

    {
        const int p  = tid & 15;
        const int c0 = tid >> 4;
        const float* xb = x + (size_t)img * 384 * 12544 + p0;
        for (int c = c0; c < 384; c += 16)
            sm[p][c] = xb[(size_t)c * 12544 + p];
    }
    __syncthreads();

    const int pix = tid >> 4;
    const int sub = tid & 15;
    const int pg = p0 + pix;
    const int h = pg / 112, w = pg % 112;
    const int win = img * 256 + (h / 7) * 16 + (w / 7);
    const int n   = (h % 7) * 7 + (w % 7);
    const size_t tw = (size_t)(win * 49 + n) * 384;       // windowed row
    const size_t tp = ((size_t)img * 12544 + pg) * 384;   // pixel-major row

    float s = 0.f, s2 = 0.f;
    for (int c = sub; c < 384; c += 16) {
        const float v = sm[pix][c] + po[tw + c];
        sm[pix][c] = v;
        s += v; s2 += v * v;
    }
    for (int o = 8; o; o >>= 1) {
        s  += __shfl_xor_sync(0xffffffffu, s,  o, 16);
        s2 += __shfl_xor_sync(0xffffffffu, s2, o, 16);
    }
    const float mean = s * (1.f/384.f);
    const float var  = s2 * (1.f/384.f) - mean * mean;
    const float rstd = rsqrtf(var + 1e-5f);

    for (int c = sub; c < 384; c += 16) {
        const float v = sm[pix][c];
        y [tp + c] = v;
        yn[tp + c] = (v - mean) * rstd * g[c] + b[c];
    }
}

// ---------------------------------------------------------------------------
// Kernel 8: NHWC (pixel-major) -> NCHW output transpose, 32x32 smem tiles.
// ---------------------------------------------------------------------------
__global__ void __launch_bounds__(256)
trans_out(const float* __restrict__ z, float* __restrict__ out)
{
    __shared__ float tile[32][33];
    const int bid = blockIdx.x;
    const int img = bid / (392 * 12);
    const int r   = bid % (392 * 12);
    const int pt  = (r / 12) * 32;
    const int ct  = (r % 12) * 32;
    const int tx = threadIdx.x & 31;
    const int ty = threadIdx.x >> 5;

#pragma unroll
    for (int i = 0; i < 4; i++) {
        const int p = ty + i * 8;
        tile[p][tx] = z[((size_t)img * 12544 + pt + p) * 384 + ct + tx];
    }
    __syncthreads();
#pragma unroll
    for (int i = 0; i < 4; i++) {
        const int c = ty + i * 8;
        out[((size_t)img * 384 + ct + c) * 12544 + pt + tx] = tile[tx][c];
    }
}

// ---------------------------------------------------------------------------
extern "C" void kernel_launch(void* const* d_in, const int* in_sizes, int n_in,
                              void* d_out, int out_size)
{
    const float* x      = (const float*)d_in[0];
    const float* g1     = (const float*)d_in[1];
    const float* b1     = (const float*)d_in[2];
    const float* w_qkv  = (const float*)d_in[3];
    const float* b_qkv  = (const float*)d_in[4];
    const float* rpb    = (const float*)d_in[5];
    const float* w_proj = (const float*)d_in[6];
    const float* b_proj = (const float*)d_in[7];
    const float* g2     = (const float*)d_in[8];
    const float* b2     = (const float*)d_in[9];
    const float* w_fc1  = (const float*)d_in[10];
    const float* b_fc1  = (const float*)d_in[11];
    const float* w_fc2  = (const float*)d_in[12];
    const float* b_fc2  = (const float*)d_in[13];
    float* out = (float*)d_out;

    float *xn, *qkv, *ao, *po, *y, *yn, *h1, *z;
    cudaGetSymbolAddress((void**)&xn,  g_xn);
    cudaGetSymbolAddress((void**)&qkv, g_qkv);
    cudaGetSymbolAddress((void**)&ao,  g_ao);
    cudaGetSymbolAddress((void**)&po,  g_po);
    cudaGetSymbolAddress((void**)&y,   g_y);
    cudaGetSymbolAddress((void**)&yn,  g_yn);
    cudaGetSymbolAddress((void**)&h1,  g_h1);
    cudaGetSymbolAddress((void**)&z,   g_z);

    // 1. LN1 + window partition
    ln1_win<<<6272, 256>>>(x, g1, b1, xn);
    // 2. QKV GEMM: (T,384)x(384,1152)
    gemm_kernel<0><<<dim3(9, 784), 256>>>(xn, w_qkv, b_qkv, nullptr, qkv,
                                          T_TOK, 1152, 384);
    // 3. windowed attention (2048 windows x 12 heads)
    attn_kernel<<<NWIN * 12, 128>>>(qkv, rpb, ao);
    // 4. proj GEMM: (T,384)x(384,384)
    gemm_kernel<0><<<dim3(3, 784), 256>>>(ao, w_proj, b_proj, nullptr, po,
                                          T_TOK, 384, 384);
    // 5. residual + LN2 (produces y and yn, pixel-major)
    res_ln2<<<6272, 256>>>(x, po, g2, b2, y, yn);
    // 6. fc1 + GELU: (T,384)x(384,1536)
    gemm_kernel<1><<<dim3(12, 784), 256>>>(yn, w_fc1, b_fc1, nullptr, h1,
                                           T_TOK, 1536, 384);
    // 7. fc2 + bias + residual y: (T,1536)x(1536,384)
    gemm_kernel<2><<<dim3(3, 784), 256>>>(h1, w_fc2, b_fc2, y, z,
                                          T_TOK, 384, 1536);
    // 8. pixel-major -> NCHW
    trans_out<<<37632, 256>>>(z, out);
}

// round 15
// speedup vs baseline: 1.2861x; 1.2861x over previous
#include <cuda_runtime.h>
#include <cuda_bf16.h>
#include <mma.h>
#include <math.h>
#include <stdint.h>

using namespace nvcuda;

// ---------------------------------------------------------------------------
// HRFormer block, B=8, C=384, H=W=112, WS=7, NH=12, head=32, HID=1536
// GEMMs on wmma (HMMA) bf16 with 2-term (hi+lo) error split:
//   D = Ahi*Bhi + Ahi*Blo + Alo*Bhi   (fp32 accumulate)
// ---------------------------------------------------------------------------

#define T_TOK 100352
#define NWIN  2048

// ---------------- scratch (device globals: allocation-free) ----------------
__device__ __nv_bfloat16 g_xnh[38535168], g_xnl[38535168];
__device__ float         g_qkv[115605504];
__device__ __nv_bfloat16 g_aoh[38535168], g_aol[38535168];
__device__ float         g_po [38535168];
__device__ float         g_y  [38535168];
__device__ __nv_bfloat16 g_ynh[38535168], g_ynl[38535168];
__device__ __nv_bfloat16 g_h1h[154140672], g_h1l[154140672];
__device__ float         g_z  [38535168];
// weights, converted to bf16 hi/lo and transposed to [N,K]
__device__ __nv_bfloat16 g_wqh[442368], g_wql[442368];
__device__ __nv_bfloat16 g_wph[147456], g_wpl[147456];
__device__ __nv_bfloat16 g_f1h[589824], g_f1l[589824];
__device__ __nv_bfloat16 g_f2h[589824], g_f2l[589824];

__device__ __forceinline__ void split_store(__nv_bfloat16* hp, __nv_bfloat16* lp,
                                            size_t idx, float v) {
    __nv_bfloat16 h = __float2bfloat16(v);
    hp[idx] = h;
    lp[idx] = __float2bfloat16(v - __bfloat162float(h));
}

// ---------------------------------------------------------------------------
// Kernel 1: LN1 over C + window partition -> bf16 hi/lo (windowed token order)
// ---------------------------------------------------------------------------
__global__ void __launch_bounds__(256)
ln1_win(const float* __restrict__ x, const float* __restrict__ g,
        const float* __restrict__ b,
        __nv_bfloat16* __restrict__ xnh, __nv_bfloat16* __restrict__ xnl)
{
    __shared__ float sm[16][388];
    const int bid = blockIdx.x;
    const int img = bid / 784;
    const int p0  = (bid % 784) * 16;
    const int tid = threadIdx.x;

    {
        const int p  = tid & 15;
        const int c0 = tid >> 4;
        const float* xb = x + (size_t)img * 384 * 12544 + p0;
        for (int c = c0; c < 384; c += 16)
            sm[p][c] = xb[(size_t)c * 12544 + p];
    }
    __syncthreads();

    const int pix = tid >> 4;
    const int sub = tid & 15;
    float s = 0.f, s2 = 0.f;
    for (int c = sub; c < 384; c += 16) { float v = sm[pix][c]; s += v; s2 += v * v; }
    for (int o = 8; o; o >>= 1) {
        s  += __shfl_xor_sync(0xffffffffu, s,  o, 16);
        s2 += __shfl_xor_sync(0xffffffffu, s2, o, 16);
    }
    const float mean = s * (1.f / 384.f);
    const float var  = s2 * (1.f / 384.f) - mean * mean;
    const float rstd = rsqrtf(var + 1e-5f);

    const int pg = p0 + pix;
    const int h = pg / 112, w = pg % 112;
    const int win = img * 256 + (h / 7) * 16 + (w / 7);
    const int n   = (h % 7) * 7 + (w % 7);
    const size_t t = (size_t)(win * 49 + n) * 384;
    for (int c = sub; c < 384; c += 16) {
        float v = (sm[pix][c] - mean) * rstd * g[c] + b[c];
        split_store(xnh, xnl, t + c, v);
    }
}

// ---------------------------------------------------------------------------
// Weight convert: W[K,N] fp32 -> Bhi/Blo[N,K] bf16 (transposed)
// ---------------------------------------------------------------------------
__global__ void __launch_bounds__(256)
wconv(const float* __restrict__ W, int K, int N,
      __nv_bfloat16* __restrict__ Oh, __nv_bfloat16* __restrict__ Ol)
{
    __shared__ float t[32][33];
    const int n0 = blockIdx.x * 32, k0 = blockIdx.y * 32;
    const int tx = threadIdx.x & 31, ty = threadIdx.x >> 5;
#pragma unroll
    for (int i = 0; i < 4; i++)
        t[ty + i * 8][tx] = W[(size_t)(k0 + ty + i * 8) * N + n0 + tx];
    __syncthreads();
#pragma unroll
    for (int i = 0; i < 4; i++) {
        const int n = ty + i * 8;
        split_store(Oh, Ol, (size_t)(n0 + n) * K + k0 + tx, t[tx][n]);
    }
}

// ---------------------------------------------------------------------------
// wmma bf16 split GEMM. Block tile 128x128, K-chunk 32, 256 threads (8 warps,
// warp grid 4(m) x 2(n), warp tile 32x64). A:[M,K] hi/lo, B:[N,K] hi/lo.
// EPI: 0 = fp32 out (+bias), 1 = GELU -> bf16 hi/lo, 2 = +bias+res -> fp32
// ---------------------------------------------------------------------------
#define GEMM_SMEM 67584   // max(4*128*40*2 = 40960 tile bytes, 128*132*4 = 67584 C bytes)
#define LDT 40            // bf16 smem row stride (padded)
#define LDC 132           // f32 epilogue smem row stride

template<int EPI>
__global__ void __launch_bounds__(256)
mma_gemm(const __nv_bfloat16* __restrict__ Ah, const __nv_bfloat16* __restrict__ Al,
         const __nv_bfloat16* __restrict__ Bh, const __nv_bfloat16* __restrict__ Bl,
         const float* __restrict__ bias, const float* __restrict__ res,
         float* __restrict__ Cf,
         __nv_bfloat16* __restrict__ Ch, __nv_bfloat16* __restrict__ Cl,
         int M, int N, int K)
{
    extern __shared__ char sraw[];
    __nv_bfloat16* sAh = (__nv_bfloat16*)sraw;            // [128][LDT]
    __nv_bfloat16* sAl = sAh + 128 * LDT;
    __nv_bfloat16* sBh = sAl + 128 * LDT;
    __nv_bfloat16* sBl = sBh + 128 * LDT;
    float*         sC  = (float*)sraw;                    // reused post-mainloop

    const int tid  = threadIdx.x;
    const int wid  = tid >> 5;
    const int wm   = wid >> 1;          // 0..3
    const int wn   = wid & 1;           // 0..1
    const int m0 = blockIdx.y * 128;
    const int n0 = blockIdx.x * 128;

    wmma::fragment<wmma::accumulator, 16, 16, 16, float> c[2][4];
#pragma unroll
    for (int i = 0; i < 2; i++)
#pragma unroll
        for (int j = 0; j < 4; j++) wmma::fill_fragment(c[i][j], 0.f);

    const int lrow = tid >> 1;          // 0..127
    const int lseg = (tid & 1) << 4;    // 0 or 16 (halves)

    for (int kb = 0; kb < K; kb += 32) {
        // ---- cooperative tile load: each thread one 16-half row segment ----
        {
            const size_t ga = (size_t)(m0 + lrow) * K + kb + lseg;
            const size_t gb = (size_t)(n0 + lrow) * K + kb + lseg;
            const int so = lrow * LDT + lseg;
            *(uint4*)(sAh + so)     = *(const uint4*)(Ah + ga);
            *(uint4*)(sAh + so + 8) = *(const uint4*)(Ah + ga + 8);
            *(uint4*)(sAl + so)     = *(const uint4*)(Al + ga);
            *(uint4*)(sAl + so + 8) = *(const uint4*)(Al + ga + 8);
            *(uint4*)(sBh + so)     = *(const uint4*)(Bh + gb);
            *(uint4*)(sBh + so + 8) = *(const uint4*)(Bh + gb + 8);
            *(uint4*)(sBl + so)     = *(const uint4*)(Bl + gb);
            *(uint4*)(sBl + so + 8) = *(const uint4*)(Bl + gb + 8);
        }
        __syncthreads();

#pragma unroll
        for (int kk = 0; kk < 32; kk += 16) {
            wmma::fragment<wmma::matrix_a, 16, 16, 16, __nv_bfloat16, wmma::row_major> ah[2], al[2];
            wmma::fragment<wmma::matrix_b, 16, 16, 16, __nv_bfloat16, wmma::col_major> bh[4], bl[4];
#pragma unroll
            for (int i = 0; i < 2; i++) {
                const int mo = (wm * 32 + i * 16) * LDT + kk;
                wmma::load_matrix_sync(ah[i], sAh + mo, LDT);
                wmma::load_matrix_sync(al[i], sAl + mo, LDT);
            }
#pragma unroll
            for (int j = 0; j < 4; j++) {
                const int no = (wn * 64 + j * 16) * LDT + kk;
                wmma::load_matrix_sync(bh[j], sBh + no, LDT);
                wmma::load_matrix_sync(bl[j], sBl + no, LDT);
            }
#pragma unroll
            for (int i = 0; i < 2; i++)
#pragma unroll
                for (int j = 0; j < 4; j++) {
                    wmma::mma_sync(c[i][j], ah[i], bh[j], c[i][j]);
                    wmma::mma_sync(c[i][j], ah[i], bl[j], c[i][j]);
                    wmma::mma_sync(c[i][j], al[i], bh[j], c[i][j]);
                }
        }
        __syncthreads();
    }

    // ---- park accumulators in smem, then generic epilogue ----
#pragma unroll
    for (int i = 0; i < 2; i++)
#pragma unroll
        for (int j = 0; j < 4; j++)
            wmma::store_matrix_sync(sC + (wm * 32 + i * 16) * LDC + wn * 64 + j * 16,
                                    c[i][j], LDC, wmma::mem_row_major);
    __syncthreads();

    const int row = tid >> 1;               // 0..127
    const int cb  = (tid & 1) * 64;         // col half within tile
    const int grow = m0 + row;
    const size_t ro = (size_t)grow * N + n0 + cb;
    const float* crow = sC + row * LDC + cb;

    if (EPI == 0) {
#pragma unroll
        for (int q = 0; q < 16; q++) {
            float4 f;
            f.x = crow[4*q+0] + __ldg(bias + n0 + cb + 4*q + 0);
            f.y = crow[4*q+1] + __ldg(bias + n0 + cb + 4*q + 1);
            f.z = crow[4*q+2] + __ldg(bias + n0 + cb + 4*q + 2);
            f.w = crow[4*q+3] + __ldg(bias + n0 + cb + 4*q + 3);
            *(float4*)(Cf + ro + 4*q) = f;
        }
    } else if (EPI == 1) {
#pragma unroll
        for (int q = 0; q < 8; q++) {
            uint32_t ph[4], pl[4];
#pragma unroll
            for (int p = 0; p < 4; p++) {
                const int cc = q * 8 + p * 2;
                float v0 = crow[cc]     + __ldg(bias + n0 + cb + cc);
                float v1 = crow[cc + 1] + __ldg(bias + n0 + cb + cc + 1);
                v0 = 0.5f * v0 * (1.f + erff(v0 * 0.7071067811865475f));
                v1 = 0.5f * v1 * (1.f + erff(v1 * 0.7071067811865475f));
                __nv_bfloat16 h0 = __float2bfloat16(v0);
                __nv_bfloat16 h1 = __float2bfloat16(v1);
                __nv_bfloat162 hh = __halves2bfloat162(h0, h1);
                __nv_bfloat162 ll = __floats2bfloat162_rn(v0 - __bfloat162float(h0),
                                                          v1 - __bfloat162float(h1));
                ph[p] = *reinterpret_cast<uint32_t*>(&hh);
                pl[p] = *reinterpret_cast<uint32_t*>(&ll);
            }
            *(uint4*)(Ch + ro + q * 8) = make_uint4(ph[0], ph[1], ph[2], ph[3]);
            *(uint4*)(Cl + ro + q * 8) = make_uint4(pl[0], pl[1], pl[2], pl[3]);
        }
    } else {  // EPI == 2
#pragma unroll
        for (int q = 0; q < 16; q++) {
            const float4 rv = *(const float4*)(res + ro + 4*q);
            float4 f;
            f.x = crow[4*q+0] + __ldg(bias + n0 + cb + 4*q + 0) + rv.x;
            f.y = crow[4*q+1] + __ldg(bias + n0 + cb + 4*q + 1) + rv.y;
            f.z = crow[4*q+2] + __ldg(bias + n0 + cb + 4*q + 2) + rv.z;
            f.w = crow[4*q+3] + __ldg(bias + n0 + cb + 4*q + 3) + rv.w;
            *(float4*)(Cf + ro + 4*q) = f;
        }
    }
}

// ---------------------------------------------------------------------------
// Kernel 3: windowed attention. One block = (window, head). 49 tokens, d=32.
// ---------------------------------------------------------------------------
__global__ void __launch_bounds__(128)
attn_kernel(const float* __restrict__ qkv, const float* __restrict__ rpb,
            __nv_bfloat16* __restrict__ aoh, __nv_bfloat16* __restrict__ aol)
{
    __shared__ float q [49][33];
    __shared__ float kk[49][33];
    __shared__ float vv[49][33];
    __shared__ float at[49][49];

    const int win  = blockIdx.x / 12;
    const int head = blockIdx.x % 12;
    const int tid  = threadIdx.x;

    const size_t base0 = (size_t)win * 49 * 1152 + head * 32;
    for (int i = tid; i < 49 * 32; i += 128) {
        const int n = i >> 5, d = i & 31;
        const size_t o = base0 + (size_t)n * 1152 + d;
        q [n][d] = qkv[o]       * 0.1767766952966369f;
        kk[n][d] = qkv[o + 384];
        vv[n][d] = qkv[o + 768];
    }
    __syncthreads();

    for (int idx = tid; idx < 49 * 49; idx += 128) {
        const int n = idx / 49, m = idx % 49;
        float s = 0.f;
#pragma unroll
        for (int d = 0; d < 32; d++) s += q[n][d] * kk[m][d];
        const int i1 = n / 7, j1 = n % 7, i2 = m / 7, j2 = m % 7;
        const int ridx = (i1 - i2 + 6) * 13 + (j1 - j2 + 6);
        at[n][m] = s + rpb[ridx * 12 + head];
    }
    __syncthreads();

    if (tid < 49) {
        const int n = tid;
        float mx = -1e30f;
        for (int m = 0; m < 49; m++) mx = fmaxf(mx, at[n][m]);
        float sum = 0.f;
        for (int m = 0; m < 49; m++) { float e = expf(at[n][m] - mx); at[n][m] = e; sum += e; }
        const float inv = 1.f / sum;
        for (int m = 0; m < 49; m++) at[n][m] *= inv;
    }
    __syncthreads();

    for (int i = tid; i < 49 * 32; i += 128) {
        const int n = i >> 5, d = i & 31;
        float s = 0.f;
#pragma unroll
        for (int m = 0; m < 49; m++) s += at[n][m] * vv[m][d];
        split_store(aoh, aol, (size_t)(win * 49 + n) * 384 + head * 32 + d, s);
    }
}

// ---------------------------------------------------------------------------
// Kernel 5: y = transpose(x) + window_reverse(proj_out); yn = LN2(y) hi/lo.
// ---------------------------------------------------------------------------
__global__ void __launch_bounds__(256)
res_ln2(const float* __restrict__ x, const float* __restrict__ po,
        const float* __restrict__ g, const float* __restrict__ b,
        float* __restrict__ y,
        __nv_bfloat16* __restrict__ ynh, __nv_bfloat16* __restrict__ ynl)
{
    __shared__ float sm[16][388];
    const int bid = blockIdx.x;
    const int img = bid / 784;
    const int p0  = (bid % 784) * 16;
    const int tid = threadIdx.x;

    {
        const int p  = tid & 15;
        const int c0 = tid >> 4;
        const float* xb = x + (size_t)img * 384 * 12544 + p0;
        for (int c = c0; c < 384; c += 16)
            sm[p][c] = xb[(size_t)c * 12544 + p];
    }
    __syncthreads();

    const int pix = tid >> 4;
    const int sub = tid & 15;
    const int pg = p0 + pix;
    const int h = pg / 112, w = pg % 112;
    const int win = img * 256 + (h / 7) * 16 + (w / 7);
    const int n   = (h % 7) * 7 + (w % 7);
    const size_t tw = (size_t)(win * 49 + n) * 384;
    const size_t tp = ((size_t)img * 12544 + pg) * 384;

    float s = 0.f, s2 = 0.f;
    for (int c = sub; c < 384; c += 16) {
        const float v = sm[pix][c] + po[tw + c];
        sm[pix][c] = v;
        s += v; s2 += v * v;
    }
    for (int o = 8; o; o >>= 1) {
        s  += __shfl_xor_sync(0xffffffffu, s,  o, 16);
        s2 += __shfl_xor_sync(0xffffffffu, s2, o, 16);
    }
    const float mean = s * (1.f / 384.f);
    const float var  = s2 * (1.f / 384.f) - mean * mean;
    const float rstd = rsqrtf(var + 1e-5f);

    for (int c = sub; c < 384; c += 16) {
        const float v = sm[pix][c];
        y[tp + c] = v;
        split_store(ynh, ynl, tp + c, (v - mean) * rstd * g[c] + b[c]);
    }
}

// ---------------------------------------------------------------------------
// Kernel 8: pixel-major NHWC -> NCHW output transpose.
// ---------------------------------------------------------------------------
__global__ void __launch_bounds__(256)
trans_out(const float* __restrict__ z, float* __restrict__ out)
{
    __shared__ float tile[32][33];
    const int bid = blockIdx.x;
    const int img = bid / (392 * 12);
    const int r   = bid % (392 * 12);
    const int pt  = (r / 12) * 32;
    const int ct  = (r % 12) * 32;
    const int tx = threadIdx.x & 31;
    const int ty = threadIdx.x >> 5;

#pragma unroll
    for (int i = 0; i < 4; i++) {
        const int p = ty + i * 8;
        tile[p][tx] = z[((size_t)img * 12544 + pt + p) * 384 + ct + tx];
    }
    __syncthreads();
#pragma unroll
    for (int i = 0; i < 4; i++) {
        const int c = ty + i * 8;
        out[((size_t)img * 384 + ct + c) * 12544 + pt + tx] = tile[tx][c];
    }
}

// ---------------------------------------------------------------------------
extern "C" void kernel_launch(void* const* d_in, const int* in_sizes, int n_in,
                              void* d_out, int out_size)
{
    const float* x      = (const float*)d_in[0];
    const float* g1     = (const float*)d_in[1];
    const float* b1     = (const float*)d_in[2];
    const float* w_qkv  = (const float*)d_in[3];
    const float* b_qkv  = (const float*)d_in[4];
    const float* rpb    = (const float*)d_in[5];
    const float* w_proj = (const float*)d_in[6];
    const float* b_proj = (const float*)d_in[7];
    const float* g2     = (const float*)d_in[8];
    const float* b2     = (const float*)d_in[9];
    const float* w_fc1  = (const float*)d_in[10];
    const float* b_fc1  = (const float*)d_in[11];
    const float* w_fc2  = (const float*)d_in[12];
    const float* b_fc2  = (const float*)d_in[13];
    float* out = (float*)d_out;

    __nv_bfloat16 *xnh, *xnl, *aoh, *aol, *ynh, *ynl, *h1h, *h1l;
    __nv_bfloat16 *wqh, *wql, *wph, *wpl, *f1h, *f1l, *f2h, *f2l;
    float *qkv, *po, *y, *z;
    cudaGetSymbolAddress((void**)&xnh, g_xnh);  cudaGetSymbolAddress((void**)&xnl, g_xnl);
    cudaGetSymbolAddress((void**)&qkv, g_qkv);
    cudaGetSymbolAddress((void**)&aoh, g_aoh);  cudaGetSymbolAddress((void**)&aol, g_aol);
    cudaGetSymbolAddress((void**)&po,  g_po);
    cudaGetSymbolAddress((void**)&y,   g_y);
    cudaGetSymbolAddress((void**)&ynh, g_ynh);  cudaGetSymbolAddress((void**)&ynl, g_ynl);
    cudaGetSymbolAddress((void**)&h1h, g_h1h);  cudaGetSymbolAddress((void**)&h1l, g_h1l);
    cudaGetSymbolAddress((void**)&z,   g_z);
    cudaGetSymbolAddress((void**)&wqh, g_wqh);  cudaGetSymbolAddress((void**)&wql, g_wql);
    cudaGetSymbolAddress((void**)&wph, g_wph);  cudaGetSymbolAddress((void**)&wpl, g_wpl);
    cudaGetSymbolAddress((void**)&f1h, g_f1h);  cudaGetSymbolAddress((void**)&f1l, g_f1l);
    cudaGetSymbolAddress((void**)&f2h, g_f2h);  cudaGetSymbolAddress((void**)&f2l, g_f2l);

    cudaFuncSetAttribute(mma_gemm<0>, cudaFuncAttributeMaxDynamicSharedMemorySize, GEMM_SMEM);
    cudaFuncSetAttribute(mma_gemm<1>, cudaFuncAttributeMaxDynamicSharedMemorySize, GEMM_SMEM);
    cudaFuncSetAttribute(mma_gemm<2>, cudaFuncAttributeMaxDynamicSharedMemorySize, GEMM_SMEM);

    // weight conversion (fp32 [K,N] -> bf16 hi/lo [N,K])
    wconv<<<dim3(36, 12), 256>>>(w_qkv, 384, 1152, wqh, wql);
    wconv<<<dim3(12, 12), 256>>>(w_proj, 384, 384, wph, wpl);
    wconv<<<dim3(48, 12), 256>>>(w_fc1, 384, 1536, f1h, f1l);
    wconv<<<dim3(12, 48), 256>>>(w_fc2, 1536, 384, f2h, f2l);

    // 1. LN1 + window partition -> bf16 hi/lo
    ln1_win<<<6272, 256>>>(x, g1, b1, xnh, xnl);
    // 2. QKV GEMM (T,384)x(384,1152) -> fp32
    mma_gemm<0><<<dim3(9, 784), 256, GEMM_SMEM>>>(xnh, xnl, wqh, wql, b_qkv,
        nullptr, qkv, nullptr, nullptr, T_TOK, 1152, 384);
    // 3. windowed attention -> bf16 hi/lo
    attn_kernel<<<NWIN * 12, 128>>>(qkv, rpb, aoh, aol);
    // 4. proj GEMM (T,384)x(384,384) -> fp32
    mma_gemm<0><<<dim3(3, 784), 256, GEMM_SMEM>>>(aoh, aol, wph, wpl, b_proj,
        nullptr, po, nullptr, nullptr, T_TOK, 384, 384);
    // 5. residual + LN2 -> y fp32, yn bf16 hi/lo (pixel order)
    res_ln2<<<6272, 256>>>(x, po, g2, b2, y, ynh, ynl);
    // 6. fc1 + GELU (T,384)x(384,1536) -> bf16 hi/lo
    mma_gemm<1><<<dim3(12, 784), 256, GEMM_SMEM>>>(ynh, ynl, f1h, f1l, b_fc1,
        nullptr, nullptr, h1h, h1l, T_TOK, 1536, 384);
    // 7. fc2 + bias + residual (T,1536)x(1536,384) -> fp32
    mma_gemm<2><<<dim3(3, 784), 256, GEMM_SMEM>>>(h1h, h1l, f2h, f2l, b_fc2,
        y, z, nullptr, nullptr, T_TOK, 384, 1536);
    // 8. pixel-major -> NCHW
    trans_out<<<37632, 256>>>(z, out);
}

// round 16
// speedup vs baseline: 1.5236x; 1.1846x over previous
#include <cuda_runtime.h>
#include <cuda_bf16.h>
#include <mma.h>
#include <math.h>
#include <stdint.h>

using namespace nvcuda;

// ---------------------------------------------------------------------------
// HRFormer block, B=8, C=384, H=W=112, WS=7, NH=12, head=32, HID=1536
// GEMMs on wmma (HMMA) bf16 with 2-term (hi+lo) error split:
//   D = Ahi*Bhi + Ahi*Blo + Alo*Bhi   (fp32 accumulate)
// Mainloop: cp.async double-buffered (2-stage) global->smem pipeline.
// ---------------------------------------------------------------------------

#define T_TOK 100352
#define NWIN  2048

// ---------------- scratch (device globals: allocation-free) ----------------
__device__ __nv_bfloat16 g_xnh[38535168], g_xnl[38535168];
__device__ float         g_qkv[115605504];
__device__ __nv_bfloat16 g_aoh[38535168], g_aol[38535168];
__device__ float         g_po [38535168];
__device__ float         g_y  [38535168];
__device__ __nv_bfloat16 g_ynh[38535168], g_ynl[38535168];
__device__ __nv_bfloat16 g_h1h[154140672], g_h1l[154140672];
__device__ float         g_z  [38535168];
// weights, converted to bf16 hi/lo and transposed to [N,K]
__device__ __nv_bfloat16 g_wqh[442368], g_wql[442368];
__device__ __nv_bfloat16 g_wph[147456], g_wpl[147456];
__device__ __nv_bfloat16 g_f1h[589824], g_f1l[589824];
__device__ __nv_bfloat16 g_f2h[589824], g_f2l[589824];

__device__ __forceinline__ void split_store(__nv_bfloat16* hp, __nv_bfloat16* lp,
                                            size_t idx, float v) {
    __nv_bfloat16 h = __float2bfloat16(v);
    hp[idx] = h;
    lp[idx] = __float2bfloat16(v - __bfloat162float(h));
}

#define CP_ASYNC16(dst_u32, src_ptr) \
    asm volatile("cp.async.cg.shared.global [%0], [%1], 16;" \
                 :: "r"(dst_u32), "l"(src_ptr))
#define CP_COMMIT() asm volatile("cp.async.commit_group;" ::: "memory")
#define CP_WAIT1()  asm volatile("cp.async.wait_group 1;" ::: "memory")
#define CP_WAIT0()  asm volatile("cp.async.wait_group 0;" ::: "memory")

// ---------------------------------------------------------------------------
// Kernel 1: LN1 over C + window partition -> bf16 hi/lo (windowed token order)
// ---------------------------------------------------------------------------
__global__ void __launch_bounds__(256)
ln1_win(const float* __restrict__ x, const float* __restrict__ g,
        const float* __restrict__ b,
        __nv_bfloat16* __restrict__ xnh, __nv_bfloat16* __restrict__ xnl)
{
    __shared__ float sm[16][388];
    const int bid = blockIdx.x;
    const int img = bid / 784;
    const int p0  = (bid % 784) * 16;
    const int tid = threadIdx.x;

    {
        const int p  = tid & 15;
        const int c0 = tid >> 4;
        const float* xb = x + (size_t)img * 384 * 12544 + p0;
        for (int c = c0; c < 384; c += 16)
            sm[p][c] = xb[(size_t)c * 12544 + p];
    }
    __syncthreads();

    const int pix = tid >> 4;
    const int sub = tid & 15;
    float s = 0.f, s2 = 0.f;
    for (int c = sub; c < 384; c += 16) { float v = sm[pix][c]; s += v; s2 += v * v; }
    for (int o = 8; o; o >>= 1) {
        s  += __shfl_xor_sync(0xffffffffu, s,  o, 16);
        s2 += __shfl_xor_sync(0xffffffffu, s2, o, 16);
    }
    const float mean = s * (1.f / 384.f);
    const float var  = s2 * (1.f / 384.f) - mean * mean;
    const float rstd = rsqrtf(var + 1e-5f);

    const int pg = p0 + pix;
    const int h = pg / 112, w = pg % 112;
    const int win = img * 256 + (h / 7) * 16 + (w / 7);
    const int n   = (h % 7) * 7 + (w % 7);
    const size_t t = (size_t)(win * 49 + n) * 384;
    for (int c = sub; c < 384; c += 16) {
        float v = (sm[pix][c] - mean) * rstd * g[c] + b[c];
        split_store(xnh, xnl, t + c, v);
    }
}

// ---------------------------------------------------------------------------
// Weight convert: W[K,N] fp32 -> Bhi/Blo[N,K] bf16 (transposed)
// ---------------------------------------------------------------------------
__global__ void __launch_bounds__(256)
wconv(const float* __restrict__ W, int K, int N,
      __nv_bfloat16* __restrict__ Oh, __nv_bfloat16* __restrict__ Ol)
{
    __shared__ float t[32][33];
    const int n0 = blockIdx.x * 32, k0 = blockIdx.y * 32;
    const int tx = threadIdx.x & 31, ty = threadIdx.x >> 5;
#pragma unroll
    for (int i = 0; i < 4; i++)
        t[ty + i * 8][tx] = W[(size_t)(k0 + ty + i * 8) * N + n0 + tx];
    __syncthreads();
#pragma unroll
    for (int i = 0; i < 4; i++) {
        const int n = ty + i * 8;
        split_store(Oh, Ol, (size_t)(n0 + n) * K + k0 + tx, t[tx][n]);
    }
}

// ---------------------------------------------------------------------------
// wmma bf16 split GEMM, cp.async double-buffered.
// Block tile 128x128, K-chunk 32, 256 threads (8 warps, 4m x 2n, warp 32x64).
// A:[M,K] hi/lo, B:[N,K] hi/lo.
// EPI: 0 = fp32 out (+bias), 1 = GELU -> bf16 hi/lo, 2 = +bias+res -> fp32
// ---------------------------------------------------------------------------
#define LDT 40                         // bf16 smem row stride (padded)
#define LDC 132                        // f32 epilogue smem row stride
#define ARR_BYTES (128 * LDT * 2)      // one array (hi or lo, A or B): 10240 B
#define STAGE_BYTES (4 * ARR_BYTES)    // 40960 B per stage
#define GEMM_SMEM (2 * STAGE_BYTES)    // 81920 B (epilogue reuses: 67584 B)

template<int EPI>
__global__ void __launch_bounds__(256)
mma_gemm(const __nv_bfloat16* __restrict__ Ah, const __nv_bfloat16* __restrict__ Al,
         const __nv_bfloat16* __restrict__ Bh, const __nv_bfloat16* __restrict__ Bl,
         const float* __restrict__ bias, const float* __restrict__ res,
         float* __restrict__ Cf,
         __nv_bfloat16* __restrict__ Ch, __nv_bfloat16* __restrict__ Cl,
         int M, int N, int K)
{
    extern __shared__ char sraw[];
    float* sC = (float*)sraw;           // reused post-mainloop

    const int tid  = threadIdx.x;
    const int wid  = tid >> 5;
    const int wm   = wid >> 1;          // 0..3
    const int wn   = wid & 1;           // 0..1
    const int m0 = blockIdx.y * 128;
    const int n0 = blockIdx.x * 128;

    wmma::fragment<wmma::accumulator, 16, 16, 16, float> c[2][4];
#pragma unroll
    for (int i = 0; i < 2; i++)
#pragma unroll
        for (int j = 0; j < 4; j++) wmma::fill_fragment(c[i][j], 0.f);

    const int lrow = tid >> 1;          // 0..127
    const int lseg = (tid & 1) << 4;    // 0 or 16 (halves)
    const int so   = lrow * LDT + lseg; // smem element offset within array

    const size_t gaBase = (size_t)(m0 + lrow) * K + lseg;
    const size_t gbBase = (size_t)(n0 + lrow) * K + lseg;

    // issue one chunk's cp.asyncs into stage `st`
    auto load_chunk = [&](int kb, int st) {
        char* base = sraw + st * STAGE_BYTES;
        const uint32_t s0 = (uint32_t)__cvta_generic_to_shared(base) + so * 2;
        const size_t ga = gaBase + kb;
        const size_t gb = gbBase + kb;
        CP_ASYNC16(s0,                  Ah + ga);
        CP_ASYNC16(s0 + 16,             Ah + ga + 8);
        CP_ASYNC16(s0 + ARR_BYTES,      Al + ga);
        CP_ASYNC16(s0 + ARR_BYTES + 16, Al + ga + 8);
        CP_ASYNC16(s0 + 2*ARR_BYTES,      Bh + gb);
        CP_ASYNC16(s0 + 2*ARR_BYTES + 16, Bh + gb + 8);
        CP_ASYNC16(s0 + 3*ARR_BYTES,      Bl + gb);
        CP_ASYNC16(s0 + 3*ARR_BYTES + 16, Bl + gb + 8);
    };

    const int nch = K >> 5;
    load_chunk(0, 0);
    CP_COMMIT();

    for (int ch = 0; ch < nch; ch++) {
        const int cur = ch & 1;
        if (ch + 1 < nch) {
            load_chunk((ch + 1) << 5, cur ^ 1);
            CP_COMMIT();
            CP_WAIT1();
        } else {
            CP_WAIT0();
        }
        __syncthreads();

        const __nv_bfloat16* sAh = (const __nv_bfloat16*)(sraw + cur * STAGE_BYTES);
        const __nv_bfloat16* sAl = sAh + 128 * LDT;
        const __nv_bfloat16* sBh = sAl + 128 * LDT;
        const __nv_bfloat16* sBl = sBh + 128 * LDT;

#pragma unroll
        for (int kk = 0; kk < 32; kk += 16) {
            wmma::fragment<wmma::matrix_a, 16, 16, 16, __nv_bfloat16, wmma::row_major> ah[2], al[2];
            wmma::fragment<wmma::matrix_b, 16, 16, 16, __nv_bfloat16, wmma::col_major> bh[4], bl[4];
#pragma unroll
            for (int i = 0; i < 2; i++) {
                const int mo = (wm * 32 + i * 16) * LDT + kk;
                wmma::load_matrix_sync(ah[i], sAh + mo, LDT);
                wmma::load_matrix_sync(al[i], sAl + mo, LDT);
            }
#pragma unroll
            for (int j = 0; j < 4; j++) {
                const int no = (wn * 64 + j * 16) * LDT + kk;
                wmma::load_matrix_sync(bh[j], sBh + no, LDT);
                wmma::load_matrix_sync(bl[j], sBl + no, LDT);
            }
#pragma unroll
            for (int i = 0; i < 2; i++)
#pragma unroll
                for (int j = 0; j < 4; j++) {
                    wmma::mma_sync(c[i][j], ah[i], bh[j], c[i][j]);
                    wmma::mma_sync(c[i][j], ah[i], bl[j], c[i][j]);
                    wmma::mma_sync(c[i][j], al[i], bh[j], c[i][j]);
                }
        }
        __syncthreads();
    }

    // ---- park accumulators in smem, then generic epilogue ----
#pragma unroll
    for (int i = 0; i < 2; i++)
#pragma unroll
        for (int j = 0; j < 4; j++)
            wmma::store_matrix_sync(sC + (wm * 32 + i * 16) * LDC + wn * 64 + j * 16,
                                    c[i][j], LDC, wmma::mem_row_major);
    __syncthreads();

    const int row = tid >> 1;               // 0..127
    const int cb  = (tid & 1) * 64;         // col half within tile
    const int grow = m0 + row;
    const size_t ro = (size_t)grow * N + n0 + cb;
    const float* crow = sC + row * LDC + cb;

    if (EPI == 0) {
#pragma unroll
        for (int q = 0; q < 16; q++) {
            float4 f;
            f.x = crow[4*q+0] + __ldg(bias + n0 + cb + 4*q + 0);
            f.y = crow[4*q+1] + __ldg(bias + n0 + cb + 4*q + 1);
            f.z = crow[4*q+2] + __ldg(bias + n0 + cb + 4*q + 2);
            f.w = crow[4*q+3] + __ldg(bias + n0 + cb + 4*q + 3);
            *(float4*)(Cf + ro + 4*q) = f;
        }
    } else if (EPI == 1) {
#pragma unroll
        for (int q = 0; q < 8; q++) {
            uint32_t ph[4], pl[4];
#pragma unroll
            for (int p = 0; p < 4; p++) {
                const int cc = q * 8 + p * 2;
                float v0 = crow[cc]     + __ldg(bias + n0 + cb + cc);
                float v1 = crow[cc + 1] + __ldg(bias + n0 + cb + cc + 1);
                v0 = 0.5f * v0 * (1.f + erff(v0 * 0.7071067811865475f));
                v1 = 0.5f * v1 * (1.f + erff(v1 * 0.7071067811865475f));
                __nv_bfloat16 h0 = __float2bfloat16(v0);
                __nv_bfloat16 h1 = __float2bfloat16(v1);
                __nv_bfloat162 hh = __halves2bfloat162(h0, h1);
                __nv_bfloat162 ll = __floats2bfloat162_rn(v0 - __bfloat162float(h0),
                                                          v1 - __bfloat162float(h1));
                ph[p] = *reinterpret_cast<uint32_t*>(&hh);
                pl[p] = *reinterpret_cast<uint32_t*>(&ll);
            }
            *(uint4*)(Ch + ro + q * 8) = make_uint4(ph[0], ph[1], ph[2], ph[3]);
            *(uint4*)(Cl + ro + q * 8) = make_uint4(pl[0], pl[1], pl[2], pl[3]);
        }
    } else {  // EPI == 2
#pragma unroll
        for (int q = 0; q < 16; q++) {
            const float4 rv = *(const float4*)(res + ro + 4*q);
            float4 f;
            f.x = crow[4*q+0] + __ldg(bias + n0 + cb + 4*q + 0) + rv.x;
            f.y = crow[4*q+1] + __ldg(bias + n0 + cb + 4*q + 1) + rv.y;
            f.z = crow[4*q+2] + __ldg(bias + n0 + cb + 4*q + 2) + rv.z;
            f.w = crow[4*q+3] + __ldg(bias + n0 + cb + 4*q + 3) + rv.w;
            *(float4*)(Cf + ro + 4*q) = f;
        }
    }
}

// ---------------------------------------------------------------------------
// Kernel 3: windowed attention. One block = (window, head). 49 tokens, d=32.
// ---------------------------------------------------------------------------
__global__ void __launch_bounds__(128)
attn_kernel(const float* __restrict__ qkv, const float* __restrict__ rpb,
            __nv_bfloat16* __restrict__ aoh, __nv_bfloat16* __restrict__ aol)
{
    __shared__ float q [49][33];
    __shared__ float kk[49][33];
    __shared__ float vv[49][33];
    __shared__ float at[49][49];

    const int win  = blockIdx.x / 12;
    const int head = blockIdx.x % 12;
    const int tid  = threadIdx.x;

    const size_t base0 = (size_t)win * 49 * 1152 + head * 32;
    for (int i = tid; i < 49 * 32; i += 128) {
        const int n = i >> 5, d = i & 31;
        const size_t o = base0 + (size_t)n * 1152 + d;
        q [n][d] = qkv[o]       * 0.1767766952966369f;
        kk[n][d] = qkv[o + 384];
        vv[n][d] = qkv[o + 768];
    }
    __syncthreads();

    for (int idx = tid; idx < 49 * 49; idx += 128) {
        const int n = idx / 49, m = idx % 49;
        float s = 0.f;
#pragma unroll
        for (int d = 0; d < 32; d++) s += q[n][d] * kk[m][d];
        const int i1 = n / 7, j1 = n % 7, i2 = m / 7, j2 = m % 7;
        const int ridx = (i1 - i2 + 6) * 13 + (j1 - j2 + 6);
        at[n][m] = s + rpb[ridx * 12 + head];
    }
    __syncthreads();

    if (tid < 49) {
        const int n = tid;
        float mx = -1e30f;
        for (int m = 0; m < 49; m++) mx = fmaxf(mx, at[n][m]);
        float sum = 0.f;
        for (int m = 0; m < 49; m++) { float e = expf(at[n][m] - mx); at[n][m] = e; sum += e; }
        const float inv = 1.f / sum;
        for (int m = 0; m < 49; m++) at[n][m] *= inv;
    }
    __syncthreads();

    for (int i = tid; i < 49 * 32; i += 128) {
        const int n = i >> 5, d = i & 31;
        float s = 0.f;
#pragma unroll
        for (int m = 0; m < 49; m++) s += at[n][m] * vv[m][d];
        split_store(aoh, aol, (size_t)(win * 49 + n) * 384 + head * 32 + d, s);
    }
}

// ---------------------------------------------------------------------------
// Kernel 5: y = transpose(x) + window_reverse(proj_out); yn = LN2(y) hi/lo.
// ---------------------------------------------------------------------------
__global__ void __launch_bounds__(256)
res_ln2(const float* __restrict__ x, const float* __restrict__ po,
        const float* __restrict__ g, const float* __restrict__ b,
        float* __restrict__ y,
        __nv_bfloat16* __restrict__ ynh, __nv_bfloat16* __restrict__ ynl)
{
    __shared__ float sm[16][388];
    const int bid = blockIdx.x;
    const int img = bid / 784;
    const int p0  = (bid % 784) * 16;
    const int tid = threadIdx.x;

    {
        const int p  = tid & 15;
        const int c0 = tid >> 4;
        const float* xb = x + (size_t)img * 384 * 12544 + p0;
        for (int c = c0; c < 384; c += 16)
            sm[p][c] = xb[(size_t)c * 12544 + p];
    }
    __syncthreads();

    const int pix = tid >> 4;
    const int sub = tid & 15;
    const int pg = p0 + pix;
    const int h = pg / 112, w = pg % 112;
    const int win = img * 256 + (h / 7) * 16 + (w / 7);
    const int n   = (h % 7) * 7 + (w % 7);
    const size_t tw = (size_t)(win * 49 + n) * 384;
    const size_t tp = ((size_t)img * 12544 + pg) * 384;

    float s = 0.f, s2 = 0.f;
    for (int c = sub; c < 384; c += 16) {
        const float v = sm[pix][c] + po[tw + c];
        sm[pix][c] = v;
        s += v; s2 += v * v;
    }
    for (int o = 8; o; o >>= 1) {
        s  += __shfl_xor_sync(0xffffffffu, s,  o, 16);
        s2 += __shfl_xor_sync(0xffffffffu, s2, o, 16);
    }
    const float mean = s * (1.f / 384.f);
    const float var  = s2 * (1.f / 384.f) - mean * mean;
    const float rstd = rsqrtf(var + 1e-5f);

    for (int c = sub; c < 384; c += 16) {
        const float v = sm[pix][c];
        y[tp + c] = v;
        split_store(ynh, ynl, tp + c, (v - mean) * rstd * g[c] + b[c]);
    }
}

// ---------------------------------------------------------------------------
// Kernel 8: pixel-major NHWC -> NCHW output transpose.
// ---------------------------------------------------------------------------
__global__ void __launch_bounds__(256)
trans_out(const float* __restrict__ z, float* __restrict__ out)
{
    __shared__ float tile[32][33];
    const int bid = blockIdx.x;
    const int img = bid / (392 * 12);
    const int r   = bid % (392 * 12);
    const int pt  = (r / 12) * 32;
    const int ct  = (r % 12) * 32;
    const int tx = threadIdx.x & 31;
    const int ty = threadIdx.x >> 5;

#pragma unroll
    for (int i = 0; i < 4; i++) {
        const int p = ty + i * 8;
        tile[p][tx] = z[((size_t)img * 12544 + pt + p) * 384 + ct + tx];
    }
    __syncthreads();
#pragma unroll
    for (int i = 0; i < 4; i++) {
        const int c = ty + i * 8;
        out[((size_t)img * 384 + ct + c) * 12544 + pt + tx] = tile[tx][c];
    }
}

// ---------------------------------------------------------------------------
extern "C" void kernel_launch(void* const* d_in, const int* in_sizes, int n_in,
                              void* d_out, int out_size)
{
    const float* x      = (const float*)d_in[0];
    const float* g1     = (const float*)d_in[1];
    const float* b1     = (const float*)d_in[2];
    const float* w_qkv  = (const float*)d_in[3];
    const float* b_qkv  = (const float*)d_in[4];
    const float* rpb    = (const float*)d_in[5];
    const float* w_proj = (const float*)d_in[6];
    const float* b_proj = (const float*)d_in[7];
    const float* g2     = (const float*)d_in[8];
    const float* b2     = (const float*)d_in[9];
    const float* w_fc1  = (const float*)d_in[10];
    const float* b_fc1  = (const float*)d_in[11];
    const float* w_fc2  = (const float*)d_in[12];
    const float* b_fc2  = (const float*)d_in[13];
    float* out = (float*)d_out;

    __nv_bfloat16 *xnh, *xnl, *aoh, *aol, *ynh, *ynl, *h1h, *h1l;
    __nv_bfloat16 *wqh, *wql, *wph, *wpl, *f1h, *f1l, *f2h, *f2l;
    float *qkv, *po, *y, *z;
    cudaGetSymbolAddress((void**)&xnh, g_xnh);  cudaGetSymbolAddress((void**)&xnl, g_xnl);
    cudaGetSymbolAddress((void**)&qkv, g_qkv);
    cudaGetSymbolAddress((void**)&aoh, g_aoh);  cudaGetSymbolAddress((void**)&aol, g_aol);
    cudaGetSymbolAddress((void**)&po,  g_po);
    cudaGetSymbolAddress((void**)&y,   g_y);
    cudaGetSymbolAddress((void**)&ynh, g_ynh);  cudaGetSymbolAddress((void**)&ynl, g_ynl);
    cudaGetSymbolAddress((void**)&h1h, g_h1h);  cudaGetSymbolAddress((void**)&h1l, g_h1l);
    cudaGetSymbolAddress((void**)&z,   g_z);
    cudaGetSymbolAddress((void**)&wqh, g_wqh);  cudaGetSymbolAddress((void**)&wql, g_wql);
    cudaGetSymbolAddress((void**)&wph, g_wph);  cudaGetSymbolAddress((void**)&wpl, g_wpl);
    cudaGetSymbolAddress((void**)&f1h, g_f1h);  cudaGetSymbolAddress((void**)&f1l, g_f1l);
    cudaGetSymbolAddress((void**)&f2h, g_f2h);  cudaGetSymbolAddress((void**)&f2l, g_f2l);

    cudaFuncSetAttribute(mma_gemm<0>, cudaFuncAttributeMaxDynamicSharedMemorySize, GEMM_SMEM);
    cudaFuncSetAttribute(mma_gemm<1>, cudaFuncAttributeMaxDynamicSharedMemorySize, GEMM_SMEM);
    cudaFuncSetAttribute(mma_gemm<2>, cudaFuncAttributeMaxDynamicSharedMemorySize, GEMM_SMEM);

    // weight conversion (fp32 [K,N] -> bf16 hi/lo [N,K])
    wconv<<<dim3(36, 12), 256>>>(w_qkv, 384, 1152, wqh, wql);
    wconv<<<dim3(12, 12), 256>>>(w_proj, 384, 384, wph, wpl);
    wconv<<<dim3(48, 12), 256>>>(w_fc1, 384, 1536, f1h, f1l);
    wconv<<<dim3(12, 48), 256>>>(w_fc2, 1536, 384, f2h, f2l);

    // 1. LN1 + window partition -> bf16 hi/lo
    ln1_win<<<6272, 256>>>(x, g1, b1, xnh, xnl);
    // 2. QKV GEMM (T,384)x(384,1152) -> fp32
    mma_gemm<0><<<dim3(9, 784), 256, GEMM_SMEM>>>(xnh, xnl, wqh, wql, b_qkv,
        nullptr, qkv, nullptr, nullptr, T_TOK, 1152, 384);
    // 3. windowed attention -> bf16 hi/lo
    attn_kernel<<<NWIN * 12, 128>>>(qkv, rpb, aoh, aol);
    // 4. proj GEMM (T,384)x(384,384) -> fp32
    mma_gemm<0><<<dim3(3, 784), 256, GEMM_SMEM>>>(aoh, aol, wph, wpl, b_proj,
        nullptr, po, nullptr, nullptr, T_TOK, 384, 384);
    // 5. residual + LN2 -> y fp32, yn bf16 hi/lo (pixel order)
    res_ln2<<<6272, 256>>>(x, po, g2, b2, y, ynh, ynl);
    // 6. fc1 + GELU (T,384)x(384,1536) -> bf16 hi/lo
    mma_gemm<1><<<dim3(12, 784), 256, GEMM_SMEM>>>(ynh, ynl, f1h, f1l, b_fc1,
        nullptr, nullptr, h1h, h1l, T_TOK, 1536, 384);
    // 7. fc2 + bias + residual (T,1536)x(1536,384) -> fp32
    mma_gemm<2><<<dim3(3, 784), 256, GEMM_SMEM>>>(h1h, h1l, f2h, f2l, b_fc2,
        y, z, nullptr, nullptr, T_TOK, 384, 1536);
    // 8. pixel-major -> NCHW
    trans_out<<<37632, 256>>>(z, out);
}